// round 1
// baseline (speedup 1.0000x reference)
#include <cuda_runtime.h>
#include <math.h>

// ---------------- problem constants ----------------
#define NEG_INF_VAL -10000000000.0f

namespace {
constexpr int BKc = 64;   // B * TOPK beams
constexpr int Hc  = 512;
constexpr int Sc  = 1024;

// float scratch offsets
constexpr int OFF_GI      = 0;                       // 64*1536
constexpr int OFF_GH      = OFF_GI + 64 * 1536;      // 98304
constexpr int OFF_Q       = OFF_GH + 64 * 1536;      // 196608
constexpr int OFF_RESULT  = OFF_Q + 64 * 512;        // 229376
constexpr int OFF_CONCAT  = OFF_RESULT + 64 * 512;   // 262144 (64x1024: [ctx | h_new])
constexpr int ZERO_END    = OFF_CONCAT + 64 * 1024;  // 327680 (zero-init region)
constexpr int OFF_HNEW    = ZERO_END;                // 327680
constexpr int OFF_QB1     = OFF_HNEW + 64 * 512;     // 360448
constexpr int OFF_ATTN    = OFF_QB1 + 64;            // 360512 (64x1024 raw scores)
constexpr int OFF_PARTM   = OFF_ATTN + 64 * 1024;    // 426048 (256)
constexpr int OFF_PARTL   = OFF_PARTM + 256;         // 426304
constexpr int OFF_PARTACC = OFF_PARTL + 256;         // 426560 (256*512)
constexpr int OFF_CTXRAW  = OFF_PARTACC + 256 * 512; // 557632
constexpr int OFF_MG      = OFF_CTXRAW + 64 * 512;   // 590400
constexpr int OFF_LG      = OFF_MG + 64;             // 590464
constexpr int OFF_TKLOG   = OFF_LG + 64;             // 590528 (64*4)
constexpr int SCR_TOTAL   = OFF_TKLOG + 256;         // 590784

// output layout (floats), tuple members concatenated in order
constexpr int O_RESULT = 0;                    // 64*512
constexpr int O_HIDDEN = 32768;                // 64*512
constexpr int O_IDX    = 65536;                // 64*4
constexpr int O_ATTNS  = 65792;                // 4*64*1024
constexpr int O_MASK   = 327936;               // 64*1024
constexpr int O_SCORES = 393472;               // 64
}

__device__ __align__(16) float g_scr[SCR_TOTAL];
__device__ int g_tkidx[256];
__device__ int g_sels[64];
__device__ int g_selsent[64];

// ---------------- zero scratch accumulators ----------------
__global__ void k_zero() {
    int i = blockIdx.x * blockDim.x + threadIdx.x;  // 320*256 = 81920 float4 = 327680 floats
    reinterpret_cast<float4*>(g_scr)[i] = make_float4(0.f, 0.f, 0.f, 0.f);
}

// ---------------- tiny GEMMs: C[64xN] += A[64xK] * op(B), split-K via atomics ----------------
// BT: C[b,j] = sum_k A[b,k] * B[j,k]
__device__ __forceinline__ void gemm_bt_dev(const float* __restrict__ A, int lda,
                                            const float* __restrict__ B, int ldb,
                                            float* __restrict__ C, int ldc,
                                            const float* __restrict__ bias) {
    __shared__ float As[32][65];
    __shared__ float Bs[32][65];
    const int t  = threadIdx.x;
    const int j0 = blockIdx.x * 64;
    const int k0 = blockIdx.y * 128;
    const int bx = (t & 15) * 4;
    const int by = (t >> 4) * 4;
    float acc[4][4] = {};
    for (int kt = 0; kt < 128; kt += 32) {
        const int kk = k0 + kt;
#pragma unroll
        for (int i = 0; i < 8; i++) {
            int idx = t + i * 256;
            int r = idx >> 5, c = idx & 31;
            As[c][r] = A[r * lda + kk + c];
            Bs[c][r] = B[(j0 + r) * ldb + kk + c];
        }
        __syncthreads();
#pragma unroll
        for (int c = 0; c < 32; c++) {
            float b0 = Bs[c][bx + 0], b1 = Bs[c][bx + 1], b2 = Bs[c][bx + 2], b3 = Bs[c][bx + 3];
#pragma unroll
            for (int r = 0; r < 4; r++) {
                float av = As[c][by + r];
                acc[r][0] += av * b0; acc[r][1] += av * b1;
                acc[r][2] += av * b2; acc[r][3] += av * b3;
            }
        }
        __syncthreads();
    }
#pragma unroll
    for (int r = 0; r < 4; r++)
#pragma unroll
        for (int cc = 0; cc < 4; cc++) {
            float v = acc[r][cc];
            if (bias != nullptr && blockIdx.y == 0) v += bias[j0 + bx + cc];
            atomicAdd(&C[(by + r) * ldc + j0 + bx + cc], v);
        }
}

// AB: C[b,n] = sum_k A[b,k] * B[k,n]
__device__ __forceinline__ void gemm_ab_dev(const float* __restrict__ A, int lda,
                                            const float* __restrict__ B, int ldb,
                                            float* __restrict__ C, int ldc) {
    __shared__ float As[32][65];
    __shared__ float Bs[32][65];
    const int t  = threadIdx.x;
    const int j0 = blockIdx.x * 64;
    const int k0 = blockIdx.y * 128;
    const int bx = (t & 15) * 4;
    const int by = (t >> 4) * 4;
    float acc[4][4] = {};
    for (int kt = 0; kt < 128; kt += 32) {
        const int kk = k0 + kt;
#pragma unroll
        for (int i = 0; i < 8; i++) {
            int idx = t + i * 256;
            int r = idx >> 5, c = idx & 31;
            As[c][r] = A[r * lda + kk + c];
        }
#pragma unroll
        for (int i = 0; i < 8; i++) {
            int idx = t + i * 256;
            int c = idx >> 6, jj = idx & 63;
            Bs[c][jj] = B[(kk + c) * ldb + j0 + jj];
        }
        __syncthreads();
#pragma unroll
        for (int c = 0; c < 32; c++) {
            float b0 = Bs[c][bx + 0], b1 = Bs[c][bx + 1], b2 = Bs[c][bx + 2], b3 = Bs[c][bx + 3];
#pragma unroll
            for (int r = 0; r < 4; r++) {
                float av = As[c][by + r];
                acc[r][0] += av * b0; acc[r][1] += av * b1;
                acc[r][2] += av * b2; acc[r][3] += av * b3;
            }
        }
        __syncthreads();
    }
#pragma unroll
    for (int r = 0; r < 4; r++)
#pragma unroll
        for (int cc = 0; cc < 4; cc++)
            atomicAdd(&C[(by + r) * ldc + j0 + bx + cc], acc[r][cc]);
}

__global__ void k_gru_gemm(const float* __restrict__ x, const float* __restrict__ h,
                           const float* __restrict__ wih, const float* __restrict__ whh) {
    if (blockIdx.z == 0) gemm_bt_dev(x, Hc, wih, Hc, g_scr + OFF_GI, 1536, nullptr);
    else                 gemm_bt_dev(h, Hc, whh, Hc, g_scr + OFF_GH, 1536, nullptr);
}
__global__ void k_gemm_q(const float* __restrict__ w1) {
    gemm_ab_dev(g_scr + OFF_HNEW, Hc, w1, Hc, g_scr + OFF_Q, Hc);
}
__global__ void k_gemm_ctx(const float* __restrict__ w2, const float* __restrict__ b2) {
    gemm_bt_dev(g_scr + OFF_CTXRAW, Hc, w2, Hc, g_scr + OFF_CONCAT, 1024, b2);
}
__global__ void k_gemm_res(const float* __restrict__ w3, const float* __restrict__ b3) {
    gemm_bt_dev(g_scr + OFF_CONCAT, 1024, w3, 1024, g_scr + OFF_RESULT, Hc, b3);
}

// ---------------- GRU gates + qb1 = h_new . b1 ----------------
__global__ void k_gate(const float* __restrict__ lh, const float* __restrict__ bih,
                       const float* __restrict__ bhh, const float* __restrict__ b1) {
    int b = blockIdx.x, j = threadIdx.x;  // block 512
    const float* gi = g_scr + OFF_GI + b * 1536;
    const float* gh = g_scr + OFF_GH + b * 1536;
    float r = 1.f / (1.f + expf(-(gi[j] + bih[j] + gh[j] + bhh[j])));
    float z = 1.f / (1.f + expf(-(gi[512 + j] + bih[512 + j] + gh[512 + j] + bhh[512 + j])));
    float n = tanhf(gi[1024 + j] + bih[1024 + j] + r * (gh[1024 + j] + bhh[1024 + j]));
    float hv = lh[b * Hc + j];
    float hn = (1.f - z) * n + z * hv;
    g_scr[OFF_HNEW + b * Hc + j] = hn;
    g_scr[OFF_CONCAT + b * 1024 + 512 + j] = hn;

    // reduce hn * b1[j] across the block -> qb1[b]
    float p = hn * b1[j];
    __shared__ float red[16];
#pragma unroll
    for (int o = 16; o; o >>= 1) p += __shfl_xor_sync(0xffffffffu, p, o);
    if ((j & 31) == 0) red[j >> 5] = p;
    __syncthreads();
    if (j < 16) {
        float v = red[j];
#pragma unroll
        for (int o = 8; o; o >>= 1) v += __shfl_xor_sync(0x0000ffffu, v, o);
        if (j == 0) g_scr[OFF_QB1 + b] = v;
    }
}

// ---------------- fused attention: score + online softmax + weighted context ----------------
// grid 256 (4 blocks per beam x 64 beams), block 256. Each block: 256 seq rows.
__global__ void k_attn(const float* __restrict__ enc, const float* __restrict__ mask) {
    constexpr float inv_div = 0.04419417382415922f;  // 1/sqrt(512)
    __shared__ float qs[512];
    __shared__ float4 chunk4[16 * 128];  // 16 rows x 512 f32 = 32KB
    __shared__ float scs[16];
    __shared__ float ws[16];
    const int t = threadIdx.x;
    const int b = blockIdx.x >> 2;
    const int p = blockIdx.x & 3;
    const int sbase = p * 256;
    const float* encb = enc + (size_t)b * Sc * Hc;

    qs[t]       = g_scr[OFF_Q + b * Hc + t] * inv_div;
    qs[t + 256] = g_scr[OFF_Q + b * Hc + t + 256] * inv_div;
    const float cb = g_scr[OFF_QB1 + b] * inv_div;

    float m = -INFINITY, l = 0.f, a0 = 0.f, a1 = 0.f;
    const int w = t >> 5, lane = t & 31;
    float* ch = reinterpret_cast<float*>(chunk4);

    for (int c = 0; c < 16; c++) {
        const int s0 = sbase + c * 16;
        __syncthreads();  // protect chunk from previous-iter readers
        const float4* g = reinterpret_cast<const float4*>(encb + (size_t)s0 * Hc);
#pragma unroll
        for (int i = 0; i < 8; i++) chunk4[t + i * 256] = g[t + i * 256];
        __syncthreads();

        // scores: warp w handles rows 2w, 2w+1
#pragma unroll
        for (int rr = 0; rr < 2; rr++) {
            const int r = w * 2 + rr;
            float d = 0.f;
#pragma unroll
            for (int kk = 0; kk < 16; kk++) {
                int k = lane + kk * 32;
                d += ch[r * 512 + k] * qs[k];
            }
#pragma unroll
            for (int o = 16; o; o >>= 1) d += __shfl_xor_sync(0xffffffffu, d, o);
            if (lane == 0) {
                float sc = d + cb + mask[b * Sc + s0 + r];
                scs[r] = sc;
                g_scr[OFF_ATTN + b * Sc + s0 + r] = sc;
            }
        }
        __syncthreads();

        float cm = scs[0];
#pragma unroll
        for (int r = 1; r < 16; r++) cm = fmaxf(cm, scs[r]);
        float nm = fmaxf(m, cm);
        float scale = expf(m - nm);
        a0 *= scale; a1 *= scale; l *= scale;
        if (t < 16) ws[t] = expf(scs[t] - nm);
        __syncthreads();

        float lsum = 0.f;
#pragma unroll
        for (int r = 0; r < 16; r++) {
            float wr = ws[r];
            lsum += wr;
            a0 += wr * ch[r * 512 + t];
            a1 += wr * ch[r * 512 + t + 256];
        }
        l += lsum;
        m = nm;
    }
    const int pid = blockIdx.x;
    if (t == 0) { g_scr[OFF_PARTM + pid] = m; g_scr[OFF_PARTL + pid] = l; }
    g_scr[OFF_PARTACC + pid * 512 + t]       = a0;
    g_scr[OFF_PARTACC + pid * 512 + t + 256] = a1;
}

// ---------------- combine partials -> ctxraw, M, L ----------------
__global__ void k_combine() {
    int b = blockIdx.x, t = threadIdx.x;  // block 256
    float pm[4], e[4];
    float M = -INFINITY;
#pragma unroll
    for (int p = 0; p < 4; p++) { pm[p] = g_scr[OFF_PARTM + b * 4 + p]; M = fmaxf(M, pm[p]); }
    float L = 0.f;
#pragma unroll
    for (int p = 0; p < 4; p++) { e[p] = expf(pm[p] - M); L += g_scr[OFF_PARTL + b * 4 + p] * e[p]; }
    float invL = 1.f / L;
#pragma unroll
    for (int h = 0; h < 2; h++) {
        int col = t + h * 256;
        float s = 0.f;
#pragma unroll
        for (int p = 0; p < 4; p++) s += e[p] * g_scr[OFF_PARTACC + (b * 4 + p) * 512 + col];
        g_scr[OFF_CTXRAW + b * Hc + col] = s * invL;
    }
    if (t == 0) { g_scr[OFF_MG + b] = M; g_scr[OFF_LG + b] = L; }
}

// ---------------- top-4 per beam (values desc, ties -> lower index) ----------------
__global__ void k_topk(const float* __restrict__ evid) {
    __shared__ float sv[1024];
    __shared__ int pick[4];
    __shared__ float pickv[4];
    __shared__ float wv[8];
    __shared__ int wi[8];
    int b = blockIdx.x, t = threadIdx.x;  // block 256
#pragma unroll
    for (int i = 0; i < 4; i++) sv[t + i * 256] = g_scr[OFF_ATTN + b * Sc + t + i * 256];
    __syncthreads();
    for (int round = 0; round < 4; round++) {
        float best = -INFINITY;
        int bi = 0x7fffffff;
#pragma unroll
        for (int u = 0; u < 4; u++) {
            int idx = t * 4 + u;
            bool skip = false;
            for (int rr = 0; rr < round; rr++) skip |= (pick[rr] == idx);
            float v = sv[idx];
            if (!skip && (v > best || (v == best && idx < bi))) { best = v; bi = idx; }
        }
#pragma unroll
        for (int o = 16; o; o >>= 1) {
            float ov = __shfl_xor_sync(0xffffffffu, best, o);
            int   oi = __shfl_xor_sync(0xffffffffu, bi, o);
            if (ov > best || (ov == best && oi < bi)) { best = ov; bi = oi; }
        }
        if ((t & 31) == 0) { wv[t >> 5] = best; wi[t >> 5] = bi; }
        __syncthreads();
        if (t == 0) {
            float bb = wv[0]; int bj = wi[0];
            for (int k = 1; k < 8; k++)
                if (wv[k] > bb || (wv[k] == bb && wi[k] < bj)) { bb = wv[k]; bj = wi[k]; }
            pick[round] = bj; pickv[round] = bb;
        }
        __syncthreads();
    }
    if (t < 4) {
        float M = g_scr[OFF_MG + b], L = g_scr[OFF_LG + b];
        // -log(exp(v-M)/L) + evid = (M - v) + log(L) + evid
        g_scr[OFF_TKLOG + b * 4 + t] = (M - pickv[t]) + logf(L) + evid[b];
        g_tkidx[b * 4 + t] = pick[t];
    }
}

// ---------------- beam selection: stable ascending rank over 16 candidates / batch ----------------
__global__ void k_select(const int* __restrict__ esi, float* __restrict__ out) {
    int t = threadIdx.x;          // 512 threads = 16 warps = 16 batches
    int wb = t >> 5, lane = t & 31;
    float v = (lane < 16) ? g_scr[OFF_TKLOG + wb * 16 + lane] : INFINITY;
    int rank = 0;
#pragma unroll
    for (int j = 0; j < 16; j++) {
        float vj = __shfl_sync(0xffffffffu, v, j);
        rank += (vj < v) || (vj == v && j < lane);
    }
    if (lane < 16 && rank < 4) {
        int k = wb * 4 + rank;
        int s = wb * 4 + (lane >> 2);
        int rr = lane & 3;
        int sent = g_tkidx[s * 4 + rr];
        g_sels[k] = s;
        g_selsent[k] = sent;
        out[O_SCORES + k] = v;
        out[O_IDX + k * 4 + 0] = (float)esi[s * 3 + 0];
        out[O_IDX + k * 4 + 1] = (float)esi[s * 3 + 1];
        out[O_IDX + k * 4 + 2] = (float)esi[s * 3 + 2];
        out[O_IDX + k * 4 + 3] = (float)sent;
    }
}

// ---------------- gathers: result, hidden, attn_scores stack, mask w/ scatter ----------------
__global__ void k_gather(const float* __restrict__ prev_scores, const float* __restrict__ mask,
                         float* __restrict__ out) {
    int i = blockIdx.x * blockDim.x + threadIdx.x;  // 768*512 = 393216 exact
    if (i < 32768) {
        int bi = i >> 9, j = i & 511;
        out[O_RESULT + i] = g_scr[OFF_RESULT + g_sels[bi] * 512 + j];
    } else if (i < 65536) {
        int j = i - 32768;
        out[O_HIDDEN + j] = g_scr[OFF_HNEW + g_sels[j >> 9] * 512 + (j & 511)];
    } else if (i < 327680) {
        int j = i - 65536;             // 4*64*1024
        int p = j >> 16;
        int rem = j & 65535;
        int bi = rem >> 10, scol = rem & 1023;
        int s = g_sels[bi];
        float v = (p < 3) ? prev_scores[p * 65536 + s * 1024 + scol]
                          : g_scr[OFF_ATTN + s * 1024 + scol];
        out[O_ATTNS + j] = v;
    } else {
        int j = i - 327680;            // 64*1024
        int bi = j >> 10, scol = j & 1023;
        int s = g_sels[bi];
        float v = (scol == g_selsent[bi]) ? NEG_INF_VAL : mask[s * 1024 + scol];
        out[O_MASK + j] = v;
    }
}

// ---------------- launch ----------------
extern "C" void kernel_launch(void* const* d_in, const int* in_sizes, int n_in,
                              void* d_out, int out_size) {
    const float* last_hidden = (const float*)d_in[0];
    const float* dec_inputs  = (const float*)d_in[1];
    const float* enc         = (const float*)d_in[2];
    const float* prev_scores = (const float*)d_in[3];
    const float* mask        = (const float*)d_in[4];
    const float* evid        = (const float*)d_in[5];
    const int*   esi         = (const int*)d_in[6];
    const float* w1  = (const float*)d_in[7];
    const float* b1  = (const float*)d_in[8];
    const float* w2  = (const float*)d_in[9];
    const float* b2  = (const float*)d_in[10];
    const float* w3  = (const float*)d_in[11];
    const float* b3  = (const float*)d_in[12];
    const float* wih = (const float*)d_in[13];
    const float* whh = (const float*)d_in[14];
    const float* bih = (const float*)d_in[15];
    const float* bhh = (const float*)d_in[16];
    float* out = (float*)d_out;

    k_zero<<<320, 256>>>();
    k_gru_gemm<<<dim3(24, 4, 2), 256>>>(dec_inputs, last_hidden, wih, whh);
    k_gate<<<64, 512>>>(last_hidden, bih, bhh, b1);
    k_gemm_q<<<dim3(8, 4), 256>>>(w1);
    k_attn<<<256, 256>>>(enc, mask);
    k_combine<<<64, 256>>>();
    k_gemm_ctx<<<dim3(8, 4), 256>>>(w2, b2);
    k_gemm_res<<<dim3(8, 8), 256>>>(w3, b3);
    k_topk<<<64, 256>>>(evid);
    k_select<<<1, 512>>>(esi, out);
    k_gather<<<768, 512>>>(prev_scores, mask, out);
}

// round 2
// speedup vs baseline: 1.4121x; 1.4121x over previous
#include <cuda_runtime.h>
#include <math.h>

#define NEG_INF_VAL -10000000000.0f

namespace {
constexpr int Hc  = 512;
constexpr int Sc  = 1024;
constexpr int KS  = 8;   // split-K for H=512 GEMMs

// float scratch offsets
constexpr int OFF_GIP     = 0;                         // 8*64*1536
constexpr int OFF_GHP     = OFF_GIP + KS * 64 * 1536;  // 786432
constexpr int OFF_QP      = OFF_GHP + KS * 64 * 1536;  // 1572864 (8*64*512)
constexpr int OFF_HNEW    = OFF_QP + KS * 64 * 512;    // 1835008
constexpr int OFF_QB1     = OFF_HNEW + 64 * 512;       // 1867776
constexpr int OFF_ATTN    = OFF_QB1 + 64;              // 1867840 (64x1024)
constexpr int OFF_PARTM   = OFF_ATTN + 64 * 1024;      // 1933376 (512)
constexpr int OFF_PARTL   = OFF_PARTM + 512;           // 1933888
constexpr int OFF_PARTACC = OFF_PARTL + 512;           // 1934400 (512*512)
constexpr int OFF_CTXRAW  = OFF_PARTACC + 512 * 512;   // 2196544
constexpr int OFF_CONCAT  = OFF_CTXRAW + 64 * 512;     // 2229312 (64x1024)
constexpr int OFF_RESULT  = OFF_CONCAT + 64 * 1024;    // 2294848
constexpr int OFF_TKLOG   = OFF_RESULT + 64 * 512;     // 2327616 (64*4)
constexpr int SCR_TOTAL   = OFF_TKLOG + 256;

// output layout (floats), tuple members concatenated in order
constexpr int O_RESULT = 0;
constexpr int O_HIDDEN = 32768;
constexpr int O_IDX    = 65536;
constexpr int O_ATTNS  = 65792;
constexpr int O_MASK   = 327936;
constexpr int O_SCORES = 393472;
}

__device__ __align__(16) float g_scr[SCR_TOTAL];
__device__ int g_tkidx[256];
__device__ int g_sels[64];
__device__ int g_selsent[64];

// ---------------- GEMM building blocks (64 rows, 64-col tiles, split-K) ----------------
// BT: C[b,j] (+)= sum_k A[b,k] * B[j,k], K-chunk = ITERS*32 at k0 = blockIdx.y*ITERS*32
template<int ITERS, bool ATOMIC>
__device__ __forceinline__ void gemm_bt(const float* __restrict__ A, int lda,
                                        const float* __restrict__ B, int ldb,
                                        float* __restrict__ C, int ldc,
                                        const float* __restrict__ bias) {
    __shared__ float As[32][65];
    __shared__ float Bs[32][65];
    const int t  = threadIdx.x;
    const int j0 = blockIdx.x * 64;
    const int k0 = blockIdx.y * (ITERS * 32);
    const int bx = (t & 15) * 4;
    const int by = (t >> 4) * 4;
    float acc[4][4] = {};
#pragma unroll
    for (int it = 0; it < ITERS; it++) {
        const int kk = k0 + it * 32;
#pragma unroll
        for (int i = 0; i < 8; i++) {
            int idx = t + i * 256;
            int r = idx >> 5, c = idx & 31;
            As[c][r] = A[r * lda + kk + c];
            Bs[c][r] = B[(j0 + r) * ldb + kk + c];
        }
        __syncthreads();
#pragma unroll
        for (int c = 0; c < 32; c++) {
            float b0 = Bs[c][bx + 0], b1 = Bs[c][bx + 1], b2 = Bs[c][bx + 2], b3 = Bs[c][bx + 3];
#pragma unroll
            for (int r = 0; r < 4; r++) {
                float av = As[c][by + r];
                acc[r][0] += av * b0; acc[r][1] += av * b1;
                acc[r][2] += av * b2; acc[r][3] += av * b3;
            }
        }
        __syncthreads();
    }
#pragma unroll
    for (int r = 0; r < 4; r++)
#pragma unroll
        for (int cc = 0; cc < 4; cc++) {
            float v = acc[r][cc];
            if (ATOMIC) {
                if (bias != nullptr && blockIdx.y == 0) v += bias[j0 + bx + cc];
                atomicAdd(&C[(by + r) * ldc + j0 + bx + cc], v);
            } else {
                C[(by + r) * ldc + j0 + bx + cc] = v;
            }
        }
}

// AB: C[b,n] = sum_k A[b,k] * B[k,n]  (partial write)
template<int ITERS>
__device__ __forceinline__ void gemm_ab(const float* __restrict__ A, int lda,
                                        const float* __restrict__ B, int ldb,
                                        float* __restrict__ C, int ldc) {
    __shared__ float As[32][65];
    __shared__ float Bs[32][65];
    const int t  = threadIdx.x;
    const int j0 = blockIdx.x * 64;
    const int k0 = blockIdx.y * (ITERS * 32);
    const int bx = (t & 15) * 4;
    const int by = (t >> 4) * 4;
    float acc[4][4] = {};
#pragma unroll
    for (int it = 0; it < ITERS; it++) {
        const int kk = k0 + it * 32;
#pragma unroll
        for (int i = 0; i < 8; i++) {
            int idx = t + i * 256;
            int r = idx >> 5, c = idx & 31;
            As[c][r] = A[r * lda + kk + c];
        }
#pragma unroll
        for (int i = 0; i < 8; i++) {
            int idx = t + i * 256;
            int c = idx >> 6, jj = idx & 63;
            Bs[c][jj] = B[(kk + c) * ldb + j0 + jj];
        }
        __syncthreads();
#pragma unroll
        for (int c = 0; c < 32; c++) {
            float b0 = Bs[c][bx + 0], b1 = Bs[c][bx + 1], b2 = Bs[c][bx + 2], b3 = Bs[c][bx + 3];
#pragma unroll
            for (int r = 0; r < 4; r++) {
                float av = As[c][by + r];
                acc[r][0] += av * b0; acc[r][1] += av * b1;
                acc[r][2] += av * b2; acc[r][3] += av * b3;
            }
        }
        __syncthreads();
    }
#pragma unroll
    for (int r = 0; r < 4; r++)
#pragma unroll
        for (int cc = 0; cc < 4; cc++)
            C[(by + r) * ldc + j0 + bx + cc] = acc[r][cc];
}

// gi/gh partials: grid (24, KS, 2), block 256
__global__ void k_gru(const float* __restrict__ x, const float* __restrict__ h,
                      const float* __restrict__ wih, const float* __restrict__ whh) {
    const float* A = blockIdx.z ? h : x;
    const float* B = blockIdx.z ? whh : wih;
    float* C = g_scr + (blockIdx.z ? OFF_GHP : OFF_GIP) + blockIdx.y * (64 * 1536);
    gemm_bt<2, false>(A, Hc, B, Hc, C, 1536, nullptr);
}

// GRU gates from partials + qb1 = h_new . b1 : grid 64, block 512
__global__ void k_gate(const float* __restrict__ lh, const float* __restrict__ bih,
                       const float* __restrict__ bhh, const float* __restrict__ b1) {
    int b = blockIdx.x, j = threadIdx.x;
    float gir = bih[j],        ghr = bhh[j];
    float giz = bih[512 + j],  ghz = bhh[512 + j];
    float gin = bih[1024 + j], ghn = bhh[1024 + j];
#pragma unroll
    for (int p = 0; p < KS; p++) {
        const float* gi = g_scr + OFF_GIP + p * (64 * 1536) + b * 1536;
        const float* gh = g_scr + OFF_GHP + p * (64 * 1536) + b * 1536;
        gir += gi[j];        ghr += gh[j];
        giz += gi[512 + j];  ghz += gh[512 + j];
        gin += gi[1024 + j]; ghn += gh[1024 + j];
    }
    float r = 1.f / (1.f + expf(-(gir + ghr)));
    float z = 1.f / (1.f + expf(-(giz + ghz)));
    float n = tanhf(gin + r * ghn);
    float hv = lh[b * Hc + j];
    float hn = (1.f - z) * n + z * hv;
    g_scr[OFF_HNEW + b * Hc + j] = hn;
    g_scr[OFF_CONCAT + b * 1024 + 512 + j] = hn;

    float p = hn * b1[j];
    __shared__ float red[16];
#pragma unroll
    for (int o = 16; o; o >>= 1) p += __shfl_xor_sync(0xffffffffu, p, o);
    if ((j & 31) == 0) red[j >> 5] = p;
    __syncthreads();
    if (j < 16) {
        float v = red[j];
#pragma unroll
        for (int o = 8; o; o >>= 1) v += __shfl_xor_sync(0x0000ffffu, v, o);
        if (j == 0) g_scr[OFF_QB1 + b] = v;
    }
}

// q partials: grid (8, KS), block 256
__global__ void k_q(const float* __restrict__ w1) {
    gemm_ab<2>(g_scr + OFF_HNEW, Hc, w1, Hc, g_scr + OFF_QP + blockIdx.y * (64 * 512), Hc);
}

// ---------------- fused attention with cp.async double buffering ----------------
// grid 512 (8 blocks/beam), block 256; each block handles 128 seq rows in 16 chunks of 8.
__device__ __forceinline__ void cp_prefetch(float4* dst, const float4* src, int t) {
#pragma unroll
    for (int i = 0; i < 4; i++) {
        unsigned d = (unsigned)__cvta_generic_to_shared(dst + t + i * 256);
        asm volatile("cp.async.cg.shared.global [%0], [%1], 16;\n" :: "r"(d), "l"(src + t + i * 256));
    }
    asm volatile("cp.async.commit_group;\n");
}

__global__ void k_attn(const float* __restrict__ enc, const float* __restrict__ mask) {
    constexpr float inv_div = 0.04419417382415922f;  // 1/sqrt(512)
    __shared__ float qs[512];
    __shared__ float4 buf[2][1024];   // 2 x (8 rows x 512 f32) = 32KB
    __shared__ float scs[8];
    __shared__ float ws[8];
    const int t = threadIdx.x;
    const int b = blockIdx.x >> 3;
    const int pslice = blockIdx.x & 7;
    const int sbase = pslice * 128;
    const float* encb = enc + (size_t)b * Sc * Hc;

    float q0 = 0.f, q1 = 0.f;
#pragma unroll
    for (int p = 0; p < KS; p++) {
        q0 += g_scr[OFF_QP + p * (64 * 512) + b * Hc + t];
        q1 += g_scr[OFF_QP + p * (64 * 512) + b * Hc + t + 256];
    }
    qs[t] = q0 * inv_div;
    qs[t + 256] = q1 * inv_div;
    float cb = 0.f;  // qb1 * inv_div
    cb = g_scr[OFF_QB1 + b] * inv_div;

    const int w = t >> 5, lane = t & 31;
    float m = -INFINITY, l = 0.f, a0 = 0.f, a1 = 0.f;

    cp_prefetch(buf[0], reinterpret_cast<const float4*>(encb + (size_t)sbase * Hc), t);

    for (int c = 0; c < 16; c++) {
        if (c < 15)
            cp_prefetch(buf[(c + 1) & 1],
                        reinterpret_cast<const float4*>(encb + (size_t)(sbase + (c + 1) * 8) * Hc), t);
        if (c < 15) asm volatile("cp.async.wait_group 1;\n");
        else        asm volatile("cp.async.wait_group 0;\n");
        __syncthreads();

        const float* ch = reinterpret_cast<const float*>(buf[c & 1]);
        const int s0 = sbase + c * 8;

        // scores: warp w handles row w (8 warps)
        {
            float d = 0.f;
#pragma unroll
            for (int kk = 0; kk < 16; kk++) {
                int k = lane + kk * 32;
                d += ch[w * 512 + k] * qs[k];
            }
#pragma unroll
            for (int o = 16; o; o >>= 1) d += __shfl_xor_sync(0xffffffffu, d, o);
            if (lane == 0) {
                float sc = d + cb + mask[b * Sc + s0 + w];
                scs[w] = sc;
                g_scr[OFF_ATTN + b * Sc + s0 + w] = sc;
            }
        }
        __syncthreads();

        float cm = scs[0];
#pragma unroll
        for (int r = 1; r < 8; r++) cm = fmaxf(cm, scs[r]);
        float nm = fmaxf(m, cm);
        float scale = expf(m - nm);
        a0 *= scale; a1 *= scale; l *= scale;
        if (t < 8) ws[t] = expf(scs[t] - nm);
        __syncthreads();

        float lsum = 0.f;
#pragma unroll
        for (int r = 0; r < 8; r++) {
            float wr = ws[r];
            lsum += wr;
            a0 += wr * ch[r * 512 + t];
            a1 += wr * ch[r * 512 + t + 256];
        }
        l += lsum;
        m = nm;
        __syncthreads();
    }
    const int pid = blockIdx.x;
    if (t == 0) { g_scr[OFF_PARTM + pid] = m; g_scr[OFF_PARTL + pid] = l; }
    g_scr[OFF_PARTACC + pid * 512 + t]       = a0;
    g_scr[OFF_PARTACC + pid * 512 + t + 256] = a1;
}

// ---------------- combine partials + zero atomic targets + top-4 ----------------
// grid 64, block 256
__global__ void k_combine(const float* __restrict__ evid) {
    __shared__ float sv[1024];
    __shared__ int pick[4];
    __shared__ float pickv[4];
    __shared__ float wv[8];
    __shared__ int wi[8];
    const int b = blockIdx.x, t = threadIdx.x;

    float pm[8], e[8];
    float M = -INFINITY;
#pragma unroll
    for (int p = 0; p < 8; p++) { pm[p] = g_scr[OFF_PARTM + b * 8 + p]; M = fmaxf(M, pm[p]); }
    float L = 0.f;
#pragma unroll
    for (int p = 0; p < 8; p++) { e[p] = expf(pm[p] - M); L += g_scr[OFF_PARTL + b * 8 + p] * e[p]; }
    float invL = 1.f / L;
#pragma unroll
    for (int h = 0; h < 2; h++) {
        int col = t + h * 256;
        float s = 0.f;
#pragma unroll
        for (int p = 0; p < 8; p++) s += e[p] * g_scr[OFF_PARTACC + (b * 8 + p) * 512 + col];
        g_scr[OFF_CTXRAW + b * Hc + col] = s * invL;
        // zero atomic targets for ctx / res GEMMs
        g_scr[OFF_CONCAT + b * 1024 + col] = 0.f;
        g_scr[OFF_RESULT + b * 512 + col] = 0.f;
    }

    // top-4 over attn scores
#pragma unroll
    for (int i = 0; i < 4; i++) sv[t + i * 256] = g_scr[OFF_ATTN + b * Sc + t + i * 256];
    __syncthreads();
    for (int round = 0; round < 4; round++) {
        float best = -INFINITY;
        int bi = 0x7fffffff;
#pragma unroll
        for (int u = 0; u < 4; u++) {
            int idx = t * 4 + u;
            bool skip = false;
            for (int rr = 0; rr < round; rr++) skip |= (pick[rr] == idx);
            float v = sv[idx];
            if (!skip && (v > best || (v == best && idx < bi))) { best = v; bi = idx; }
        }
#pragma unroll
        for (int o = 16; o; o >>= 1) {
            float ov = __shfl_xor_sync(0xffffffffu, best, o);
            int   oi = __shfl_xor_sync(0xffffffffu, bi, o);
            if (ov > best || (ov == best && oi < bi)) { best = ov; bi = oi; }
        }
        if ((t & 31) == 0) { wv[t >> 5] = best; wi[t >> 5] = bi; }
        __syncthreads();
        if (t == 0) {
            float bb = wv[0]; int bj = wi[0];
            for (int k = 1; k < 8; k++)
                if (wv[k] > bb || (wv[k] == bb && wi[k] < bj)) { bb = wv[k]; bj = wi[k]; }
            pick[round] = bj; pickv[round] = bb;
        }
        __syncthreads();
    }
    if (t < 4) {
        g_scr[OFF_TKLOG + b * 4 + t] = (M - pickv[t]) + logf(L) + evid[b];
        g_tkidx[b * 4 + t] = pick[t];
    }
}

// ---------------- beam selection ----------------
__global__ void k_select(const int* __restrict__ esi, float* __restrict__ out) {
    int t = threadIdx.x;
    int wb = t >> 5, lane = t & 31;
    float v = (lane < 16) ? g_scr[OFF_TKLOG + wb * 16 + lane] : INFINITY;
    int rank = 0;
#pragma unroll
    for (int j = 0; j < 16; j++) {
        float vj = __shfl_sync(0xffffffffu, v, j);
        rank += (vj < v) || (vj == v && j < lane);
    }
    if (lane < 16 && rank < 4) {
        int k = wb * 4 + rank;
        int s = wb * 4 + (lane >> 2);
        int rr = lane & 3;
        int sent = g_tkidx[s * 4 + rr];
        g_sels[k] = s;
        g_selsent[k] = sent;
        out[O_SCORES + k] = v;
        out[O_IDX + k * 4 + 0] = (float)esi[s * 3 + 0];
        out[O_IDX + k * 4 + 1] = (float)esi[s * 3 + 1];
        out[O_IDX + k * 4 + 2] = (float)esi[s * 3 + 2];
        out[O_IDX + k * 4 + 3] = (float)sent;
    }
}

// ctx GEMM: concat[:, :512] += ctxraw @ w2^T + b2 ; grid (8, KS)
__global__ void k_ctx(const float* __restrict__ w2, const float* __restrict__ b2) {
    gemm_bt<2, true>(g_scr + OFF_CTXRAW, Hc, w2, Hc, g_scr + OFF_CONCAT, 1024, b2);
}
// result GEMM: result += concat @ w3^T + b3 ; grid (8, 8), K=1024
__global__ void k_res(const float* __restrict__ w3, const float* __restrict__ b3) {
    gemm_bt<4, true>(g_scr + OFF_CONCAT, 1024, w3, 1024, g_scr + OFF_RESULT, Hc, b3);
}

// ---------------- gathers ----------------
__global__ void k_gather(const float* __restrict__ prev_scores, const float* __restrict__ mask,
                         float* __restrict__ out) {
    int i = blockIdx.x * blockDim.x + threadIdx.x;  // 768*512 = 393216 exact
    if (i < 32768) {
        int bi = i >> 9, j = i & 511;
        out[O_RESULT + i] = g_scr[OFF_RESULT + g_sels[bi] * 512 + j];
    } else if (i < 65536) {
        int j = i - 32768;
        out[O_HIDDEN + j] = g_scr[OFF_HNEW + g_sels[j >> 9] * 512 + (j & 511)];
    } else if (i < 327680) {
        int j = i - 65536;
        int p = j >> 16;
        int rem = j & 65535;
        int bi = rem >> 10, scol = rem & 1023;
        int s = g_sels[bi];
        float v = (p < 3) ? prev_scores[p * 65536 + s * 1024 + scol]
                          : g_scr[OFF_ATTN + s * 1024 + scol];
        out[O_ATTNS + j] = v;
    } else {
        int j = i - 327680;
        int bi = j >> 10, scol = j & 1023;
        int s = g_sels[bi];
        float v = (scol == g_selsent[bi]) ? NEG_INF_VAL : mask[s * 1024 + scol];
        out[O_MASK + j] = v;
    }
}

// ---------------- launch ----------------
extern "C" void kernel_launch(void* const* d_in, const int* in_sizes, int n_in,
                              void* d_out, int out_size) {
    const float* last_hidden = (const float*)d_in[0];
    const float* dec_inputs  = (const float*)d_in[1];
    const float* enc         = (const float*)d_in[2];
    const float* prev_scores = (const float*)d_in[3];
    const float* mask        = (const float*)d_in[4];
    const float* evid        = (const float*)d_in[5];
    const int*   esi         = (const int*)d_in[6];
    const float* w1  = (const float*)d_in[7];
    const float* b1  = (const float*)d_in[8];
    const float* w2  = (const float*)d_in[9];
    const float* b2  = (const float*)d_in[10];
    const float* w3  = (const float*)d_in[11];
    const float* b3  = (const float*)d_in[12];
    const float* wih = (const float*)d_in[13];
    const float* whh = (const float*)d_in[14];
    const float* bih = (const float*)d_in[15];
    const float* bhh = (const float*)d_in[16];
    float* out = (float*)d_out;

    k_gru<<<dim3(24, KS, 2), 256>>>(dec_inputs, last_hidden, wih, whh);
    k_gate<<<64, 512>>>(last_hidden, bih, bhh, b1);
    k_q<<<dim3(8, KS), 256>>>(w1);
    k_attn<<<512, 256>>>(enc, mask);
    k_combine<<<64, 256>>>(evid);
    k_select<<<1, 512>>>(esi, out);
    k_ctx<<<dim3(8, KS), 256>>>(w2, b2);
    k_res<<<dim3(8, 8), 256>>>(w3, b3);
    k_gather<<<768, 512>>>(prev_scores, mask, out);
}